// round 1
// baseline (speedup 1.0000x reference)
#include <cuda_runtime.h>

// AdaptivePooling2D: [16,225,225,256] f32 -> [16,7,7,256] f32 (channels_last)
// All adaptive windows are [32*o, 32*o+33) with weight 1/33 (verified against
// TF fp32 index math). Separable: pool rows into scratch, then pool cols.

#define BB 16
#define HH 225
#define WW 225
#define CC 256
#define OX 7
#define OY 7
#define WIN 33
#define STRIDE 32
#define C4 (CC / 4)   // 64 float4 per pixel

// Static scratch: [B][OX][W][C4] float4 = 16*7*225*64*16B = 25.8 MB
__device__ float4 g_scratch[BB * OX * WW * C4];

// ---------------------------------------------------------------------------
// Pass 1: pool over H.  One thread = one float4 of scratch.
// scratch[b,ox,w,c4] = (1/33) * sum_{i<33} in[b, 32*ox+i, w, c4]
// ---------------------------------------------------------------------------
__global__ void __launch_bounds__(256) pool_rows_kernel(const float4* __restrict__ in)
{
    const int N = BB * OX * WW * C4;
    int idx = blockIdx.x * blockDim.x + threadIdx.x;
    if (idx >= N) return;

    int c4 = idx & (C4 - 1);        // 0..63
    int t  = idx >> 6;
    int w  = t % WW;
    t /= WW;
    int ox = t % OX;
    int b  = t / OX;

    int h0 = ox * STRIDE;
    const float4* __restrict__ p =
        in + ((size_t)(b * HH + h0) * WW + w) * C4 + c4;
    const size_t row_stride = (size_t)WW * C4;   // float4 units between rows

    float4 acc = make_float4(0.f, 0.f, 0.f, 0.f);
#pragma unroll
    for (int i = 0; i < WIN; ++i) {
        float4 v = __ldg(p + (size_t)i * row_stride);
        acc.x += v.x; acc.y += v.y; acc.z += v.z; acc.w += v.w;
    }
    const float s = 1.0f / 33.0f;
    acc.x *= s; acc.y *= s; acc.z *= s; acc.w *= s;
    g_scratch[idx] = acc;
}

// ---------------------------------------------------------------------------
// Pass 2: pool over W.  One thread = one float4 of final output.
// out[b,ox,oy,c4] = (1/33) * sum_{i<33} scratch[b,ox, 32*oy+i, c4]
// ---------------------------------------------------------------------------
__global__ void __launch_bounds__(256) pool_cols_kernel(float4* __restrict__ out)
{
    const int N = BB * OX * OY * C4;
    int idx = blockIdx.x * blockDim.x + threadIdx.x;
    if (idx >= N) return;

    int c4 = idx & (C4 - 1);
    int t  = idx >> 6;
    int oy = t % OY;
    t /= OY;
    int ox = t % OX;
    int b  = t / OX;

    int w0 = oy * STRIDE;
    const float4* __restrict__ p =
        g_scratch + ((size_t)(b * OX + ox) * WW + w0) * C4 + c4;

    float4 acc = make_float4(0.f, 0.f, 0.f, 0.f);
#pragma unroll
    for (int i = 0; i < WIN; ++i) {
        float4 v = p[(size_t)i * C4];
        acc.x += v.x; acc.y += v.y; acc.z += v.z; acc.w += v.w;
    }
    const float s = 1.0f / 33.0f;
    acc.x *= s; acc.y *= s; acc.z *= s; acc.w *= s;
    out[idx] = acc;
}

// ---------------------------------------------------------------------------
extern "C" void kernel_launch(void* const* d_in, const int* in_sizes, int n_in,
                              void* d_out, int out_size)
{
    (void)in_sizes; (void)n_in; (void)out_size;
    const float4* in  = (const float4*)d_in[0];
    float4*       out = (float4*)d_out;

    const int n1 = BB * OX * WW * C4;   // 1,612,800 threads
    const int n2 = BB * OX * OY * C4;   //    50,176 threads

    pool_rows_kernel<<<(n1 + 255) / 256, 256>>>(in);
    pool_cols_kernel<<<(n2 + 255) / 256, 256>>>(out);
}

// round 2
// speedup vs baseline: 1.0269x; 1.0269x over previous
#include <cuda_runtime.h>

// AdaptivePooling2D: [16,225,225,256] f32 -> [16,7,7,256] f32 (channels_last)
// All adaptive windows are [32*o, 32*o+33) with weight 1/33 in each dim.
// Fused single-pass: each thread owns one (b, w, c4) column, reads all 225
// rows EXACTLY ONCE (boundary rows shared between adjacent windows via a
// carried register), and atomically scatters each completed 33-row column
// sum into the 1-2 output bins whose column window contains w.

#define BB 16
#define HH 225
#define WW 225
#define C4 64            // 256 channels / 4 (float4)
#define OX 7
#define OY 7

__global__ void __launch_bounds__(256)
pool_fused_kernel(const float4* __restrict__ in, float* __restrict__ out)
{
    const int N = BB * WW * C4;            // 230,400 threads
    int idx = blockIdx.x * blockDim.x + threadIdx.x;
    if (idx >= N) return;

    const int c4 = idx & (C4 - 1);
    int t = idx >> 6;
    const int w = t % WW;
    const int b = t / WW;

    // Column-window (oy) membership of this w: always oy0; also oy1 if w is
    // a shared boundary column (w = 32k, 1 <= k <= 6).
    const int k   = w >> 5;
    const int oy0 = (k < OY) ? k : (OY - 1);
    const bool dual = ((w & 31) == 0) && (k >= 1) && (k <= 6);
    const int oy1 = k - 1;

    const float4* __restrict__ p =
        in + ((size_t)(b * HH) * WW + w) * C4 + c4;      // h = 0
    const size_t rs = (size_t)WW * C4;                    // row stride (float4)

    const float s = 1.0f / (33.0f * 33.0f);

    // Load h=0 to seed the first window.
    float4 v = __ldg(p);
    p += rs;

#pragma unroll 1
    for (int ox = 0; ox < OX; ++ox) {
        // acc starts with the boundary row 32*ox (already loaded as the last
        // row of the previous window, or h=0 for ox=0).
        float4 acc = v;
#pragma unroll 8
        for (int i = 0; i < 32; ++i) {
            v = __ldg(p);
            p += rs;
            acc.x += v.x; acc.y += v.y; acc.z += v.z; acc.w += v.w;
        }
        // acc now holds sum of rows [32*ox, 32*ox+32] (33 rows);
        // v holds row 32*ox+32, the seed for window ox+1.

        const float rx = acc.x * s, ry = acc.y * s,
                    rz = acc.z * s, rw = acc.w * s;

        float* o0 = out + ((((size_t)(b * OX + ox) * OY + oy0) * C4 + c4) << 2);
        atomicAdd(o0 + 0, rx);
        atomicAdd(o0 + 1, ry);
        atomicAdd(o0 + 2, rz);
        atomicAdd(o0 + 3, rw);
        if (dual) {
            float* o1 = out + ((((size_t)(b * OX + ox) * OY + oy1) * C4 + c4) << 2);
            atomicAdd(o1 + 0, rx);
            atomicAdd(o1 + 1, ry);
            atomicAdd(o1 + 2, rz);
            atomicAdd(o1 + 3, rw);
        }
    }
}

extern "C" void kernel_launch(void* const* d_in, const int* in_sizes, int n_in,
                              void* d_out, int out_size)
{
    (void)in_sizes; (void)n_in;
    const float4* in = (const float4*)d_in[0];
    float* out = (float*)d_out;

    // Output is poisoned (0xAA) by the harness; atomics need zeros.
    cudaMemsetAsync(d_out, 0, (size_t)out_size * sizeof(float));

    const int n = BB * WW * C4;   // 230,400
    pool_fused_kernel<<<(n + 255) / 256, 256>>>(in, out);
}

// round 3
// speedup vs baseline: 1.0407x; 1.0135x over previous
#include <cuda_runtime.h>

// AdaptivePooling2D: [16,225,225,256] f32 -> [16,7,7,256] f32 (channels_last)
// All adaptive windows are [32*o, 32*o+33), weight 1/33 per dim.
// Fused atomic-scatter, window-PAIR granularity:
//   thread = (b, w, c4, pair). pair 0..2 -> windows {2p,2p+1} (65 rows, the
//   middle boundary row carried in a register); pair 3 -> window 6 (33 rows).
//   Only rows 64/128/192 are read twice per column -> ~840 MB total traffic.
//   3600 CTAs (~4 waves) so CTA-completion spread is absorbed by later waves
//   (round-2's 900 single-wave CTAs lost ~8% HBM rate to straggler tail).

#define BB 16
#define HH 225
#define WW 225
#define C4 64            // 256 channels / 4 (float4)
#define OX 7
#define OY 7

__global__ void __launch_bounds__(256)
pool_fused_pair_kernel(const float4* __restrict__ in, float* __restrict__ out)
{
    const int N = BB * WW * C4 * 4;        // 921,600 threads
    int idx = blockIdx.x * blockDim.x + threadIdx.x;
    if (idx >= N) return;

    const int c4 = idx & (C4 - 1);
    int t = idx >> 6;
    const int w  = t % WW;
    t /= WW;
    const int pr = t & 3;                  // window pair 0..3
    const int b  = t >> 2;

    const int nwin = (pr < 3) ? 2 : 1;
    const int h0 = pr * 64;

    // Column-window (oy) membership of this w: always oy0; also oy1 if w is
    // a shared boundary column (w = 32k, 1 <= k <= 6).
    const int k   = w >> 5;
    const int oy0 = (k < OY) ? k : (OY - 1);
    const bool dual = ((w & 31) == 0) && (k >= 1) && (k <= 6);
    const int oy1 = k - 1;

    const float4* __restrict__ p =
        in + ((size_t)(b * HH + h0) * WW + w) * C4 + c4;
    const size_t rs = (size_t)WW * C4;     // row stride in float4 units

    const float s = 1.0f / (33.0f * 33.0f);

    // Seed with row h0 (first row of the first window in this pair).
    float4 v = __ldg(p);
    p += rs;

#pragma unroll 1
    for (int j = 0; j < nwin; ++j) {
        const int ox = pr * 2 + j;
        float4 acc = v;                    // boundary/seed row
#pragma unroll 8
        for (int i = 0; i < 32; ++i) {
            v = __ldg(p);
            p += rs;
            acc.x += v.x; acc.y += v.y; acc.z += v.z; acc.w += v.w;
        }
        // acc = sum of 33 rows [32*ox, 32*ox+32]; v = row 32*ox+32 seeds j+1.

        const float rx = acc.x * s, ry = acc.y * s,
                    rz = acc.z * s, rw = acc.w * s;

        float* o0 = out + ((((size_t)(b * OX + ox) * OY + oy0) * C4 + c4) << 2);
        atomicAdd(o0 + 0, rx);
        atomicAdd(o0 + 1, ry);
        atomicAdd(o0 + 2, rz);
        atomicAdd(o0 + 3, rw);
        if (dual) {
            float* o1 = out + ((((size_t)(b * OX + ox) * OY + oy1) * C4 + c4) << 2);
            atomicAdd(o1 + 0, rx);
            atomicAdd(o1 + 1, ry);
            atomicAdd(o1 + 2, rz);
            atomicAdd(o1 + 3, rw);
        }
    }
}

extern "C" void kernel_launch(void* const* d_in, const int* in_sizes, int n_in,
                              void* d_out, int out_size)
{
    (void)in_sizes; (void)n_in;
    const float4* in = (const float4*)d_in[0];
    float* out = (float*)d_out;

    // Output is poisoned (0xAA) by the harness; atomics need zeros.
    cudaMemsetAsync(d_out, 0, (size_t)out_size * sizeof(float));

    const int n = BB * WW * C4 * 4;        // 921,600
    pool_fused_pair_kernel<<<(n + 255) / 256, 256>>>(in, out);
}

// round 4
// speedup vs baseline: 1.0847x; 1.0422x over previous
#include <cuda_runtime.h>

// AdaptivePooling2D: [16,225,225,256] f32 -> [16,7,7,256] f32 (channels_last)
// Windows: [32*o, 32*o+33) in both dims, weight 1/33 each (1/1089 combined).
//
// Round-4 design: thread = (b, c4, grp, ox) sums an 8-column x 33-row
// sub-window locally, then does ONE 4-float atomic scatter (plus one more for
// the shared boundary column w=32k, tracked separately). Atomics drop from
// 6.45M (round 3) to ~1.0M, removing LTS contention with the load stream.
// Columns are read exactly once; only boundary rows re-read -> 851 MB.
// Grid = 1624 CTAs of 128 = 148*11 - 4 -> near-perfect SM residency balance.

#define BB 16
#define HH 225
#define WW 225
#define C4 64            // 256 channels / 4 (float4)
#define OX 7
#define OY 7
#define NGRP 29          // w-groups: 28 groups of 8 (w 0..223) + 1 group {224}

__global__ void __launch_bounds__(128)
pool_grouped_kernel(const float4* __restrict__ in, float* __restrict__ out)
{
    const int N = BB * C4 * NGRP * OX;     // 207,872 threads
    int idx = blockIdx.x * blockDim.x + threadIdx.x;
    if (idx >= N) return;

    const int c4 = idx & (C4 - 1);
    int t = idx >> 6;
    const int ox  = t % OX;
    t /= OX;
    const int grp = t % NGRP;
    const int b   = t / NGRP;

    const int w0 = grp * 8;
    const int h0 = ox * 32;

    // Primary output column window; cap w=224 (k=7) into window 6.
    const int k   = grp >> 2;
    const int oyP = (k < OY) ? k : (OY - 1);
    // First column of this group is a shared boundary column (w = 32k,
    // 1 <= k <= 6): its column-sum also feeds window k-1.
    const bool dual = ((grp & 3) == 0) && (grp >= 4) && (grp <= 24);
    const int oyD = k - 1;

    const float4* __restrict__ p =
        in + ((size_t)(b * HH + h0) * WW + w0) * C4 + c4;
    const size_t rs = (size_t)WW * C4;     // row stride in float4 units

    float4 acc  = make_float4(0.f, 0.f, 0.f, 0.f);  // all columns in group
    float4 acc0 = make_float4(0.f, 0.f, 0.f, 0.f);  // column j=0 only

    if (grp == NGRP - 1) {
        // Last group: single column w=224.
#pragma unroll 3
        for (int i = 0; i < 33; ++i) {
            float4 v = __ldg(p);
            p += rs;
            acc.x += v.x; acc.y += v.y; acc.z += v.z; acc.w += v.w;
        }
    } else {
#pragma unroll 2
        for (int i = 0; i < 33; ++i) {
            float4 v0 = __ldg(p + 0 * C4);
            float4 v1 = __ldg(p + 1 * C4);
            float4 v2 = __ldg(p + 2 * C4);
            float4 v3 = __ldg(p + 3 * C4);
            float4 v4 = __ldg(p + 4 * C4);
            float4 v5 = __ldg(p + 5 * C4);
            float4 v6 = __ldg(p + 6 * C4);
            float4 v7 = __ldg(p + 7 * C4);
            p += rs;

            acc0.x += v0.x; acc0.y += v0.y; acc0.z += v0.z; acc0.w += v0.w;

            float sx = v0.x + v1.x + v2.x + v3.x + v4.x + v5.x + v6.x + v7.x;
            float sy = v0.y + v1.y + v2.y + v3.y + v4.y + v5.y + v6.y + v7.y;
            float sz = v0.z + v1.z + v2.z + v3.z + v4.z + v5.z + v6.z + v7.z;
            float sw = v0.w + v1.w + v2.w + v3.w + v4.w + v5.w + v6.w + v7.w;
            acc.x += sx; acc.y += sy; acc.z += sz; acc.w += sw;
        }
    }

    const float s = 1.0f / (33.0f * 33.0f);

    float* o0 = out + ((((size_t)(b * OX + ox) * OY + oyP) * C4 + c4) << 2);
    atomicAdd(o0 + 0, acc.x * s);
    atomicAdd(o0 + 1, acc.y * s);
    atomicAdd(o0 + 2, acc.z * s);
    atomicAdd(o0 + 3, acc.w * s);

    if (dual) {
        float* o1 = out + ((((size_t)(b * OX + ox) * OY + oyD) * C4 + c4) << 2);
        atomicAdd(o1 + 0, acc0.x * s);
        atomicAdd(o1 + 1, acc0.y * s);
        atomicAdd(o1 + 2, acc0.z * s);
        atomicAdd(o1 + 3, acc0.w * s);
    }
}

extern "C" void kernel_launch(void* const* d_in, const int* in_sizes, int n_in,
                              void* d_out, int out_size)
{
    (void)in_sizes; (void)n_in;
    const float4* in = (const float4*)d_in[0];
    float* out = (float*)d_out;

    // Output is poisoned (0xAA) by the harness; atomics need zeros.
    cudaMemsetAsync(d_out, 0, (size_t)out_size * sizeof(float));

    const int n = BB * C4 * NGRP * OX;     // 207,872
    pool_grouped_kernel<<<(n + 127) / 128, 128>>>(in, out);
}